// round 10
// baseline (speedup 1.0000x reference)
#include <cuda_runtime.h>

#define BB 64
#define HH 56
#define WW 56
#define CC 256
#define COUT 64
#define ROUTES 4
#define RW (CC / ROUTES)          // 64 channels per route
#define RCHUNKS 14                // 4 rows per chunk
#define SLOTS 9                   // 3x3 (dh,dw) classes
#define GTILES 49                 // 64-pixel gather tiles per batch

// per-(batch,chunk) partial patch sums: [BB][RCHUNKS][SLOTS][CC] floats (~8 MB)
__device__ float g_S2[BB * RCHUNKS * SLOTS * CC];
__device__ int   g_cnt[BB];           // patch completion counters (self-resetting)
__device__ int   g_gcnt[BB];          // gather completion counters (self-resetting)
__device__ volatile int g_ready[BB];  // route-ready flags (self-resetting)
__device__ int   g_route[BB];

__device__ __forceinline__ float4 f4add(float4 a, float4 b) {
    return make_float4(a.x + b.x, a.y + b.y, a.z + b.z, a.w + b.w);
}
__device__ __forceinline__ float4 f4sub(float4 a, float4 b) {
    return make_float4(a.x - b.x, a.y - b.y, a.z - b.z, a.w - b.w);
}

// ---------------------------------------------------------------------------
// ONE kernel, grid = 896 blocks = (batch, chunk) b-major.
// Phase 1 (all blocks): stream 4 input rows -> 9-slot patch partial -> g_S2.
// Phase 2 (last block per batch): reduce 14 partials, 2304x64 pooled GEMM,
//          dense(4), argmax -> g_route[b], release g_ready[b].
// Phase 3 (all 14 blocks of batch b): wait g_ready[b] (own-batch only ->
//          deadlock-free: sibling bids are contiguous; other batches' blocks
//          exit independently and free slots), then copy a static slice of
//          the batch's 49 gather tiles. Last gatherer resets flags.
// No dedicated spinner blocks -> no residency pollution (the R9 failure).
// ---------------------------------------------------------------------------
__global__ __launch_bounds__(256) void routing_fused_kernel(const float* __restrict__ in,
                                                            const float* __restrict__ conv_w,
                                                            const float* __restrict__ conv_b,
                                                            const float* __restrict__ fc_w,
                                                            const float* __restrict__ fc_b,
                                                            float* __restrict__ out_logits,
                                                            float* __restrict__ out_x) {
    const int bid   = blockIdx.x;
    const int b     = bid / RCHUNKS;
    const int chunk = bid % RCHUNKS;
    const int tid   = threadIdx.x;
    const int q     = tid & 63;            // channel quad 0..63
    const int rt    = tid >> 6;            // row-thread 0..3
    const int h     = chunk * 4 + rt;

    // ================= PHASE 1: patch streaming =================
    const float4* row = (const float4*)in
                      + ((size_t)(b * HH + h) * WW) * (CC / 4) + q;

    float4 e = make_float4(0.f, 0.f, 0.f, 0.f);
    float4 o = make_float4(0.f, 0.f, 0.f, 0.f);
    float4 v0, v54, v55;
#pragma unroll
    for (int w = 0; w < WW; w += 2) {
        float4 a  = row[(size_t)w * (CC / 4)];
        float4 bb = row[(size_t)(w + 1) * (CC / 4)];
        if (w == 0)  { v0 = a; }
        if (w == 54) { v54 = a; v55 = bb; }
        e = f4add(e, a);
        o = f4add(o, bb);
    }

    __shared__ float4 sacc[4][3][64];
    sacc[rt][0][q] = f4sub(e, v54);  // W0: even w in [0,52]
    sacc[rt][1][q] = f4sub(o, v55);  // W1: odd  w in [1,53]
    sacc[rt][2][q] = f4sub(e, v0);   // W2: even w in [2,54]
    __syncthreads();

    if (rt == 0) {
        float4 outv[SLOTS];
#pragma unroll
        for (int s = 0; s < SLOTS; s++) outv[s] = make_float4(0.f, 0.f, 0.f, 0.f);

#pragma unroll
        for (int r = 0; r < 4; r++) {
            const int hh = chunk * 4 + r;
            const float4 W0 = sacc[r][0][q];
            const float4 W1 = sacc[r][1][q];
            const float4 W2 = sacc[r][2][q];
            if ((hh & 1) == 0) {
                if (hh <= 52) { outv[0] = f4add(outv[0], W0); outv[1] = f4add(outv[1], W1); outv[2] = f4add(outv[2], W2); }
                if (hh >= 2)  { outv[6] = f4add(outv[6], W0); outv[7] = f4add(outv[7], W1); outv[8] = f4add(outv[8], W2); }
            } else {
                if (hh <= 53) { outv[3] = f4add(outv[3], W0); outv[4] = f4add(outv[4], W1); outv[5] = f4add(outv[5], W2); }
            }
        }

        float4* dst = (float4*)g_S2 + ((size_t)(b * RCHUNKS + chunk) * SLOTS) * (CC / 4) + q;
#pragma unroll
        for (int s = 0; s < SLOTS; s++)
            dst[(size_t)s * (CC / 4)] = outv[s];
    }
    __syncthreads();

    // ---- per-batch completion counter -------------------------------------
    __shared__ int s_last;
    if (tid == 0) {
        __threadfence();                           // publish g_S2 stores
        int old = atomicAdd(&g_cnt[b], 1);
        s_last = (old == RCHUNKS - 1);
        if (s_last) g_cnt[b] = 0;                  // reset for next replay
    }
    __syncthreads();

    // ================= PHASE 2: routing tail (last block of batch) ==========
    if (s_last) {
        if (tid == 0) __threadfence();             // acquire side
        __syncthreads();

        __shared__ __align__(16) float sS[SLOTS * CC];
        for (int i = tid; i < SLOTS * CC / 4; i += 256) {
            float4 s = make_float4(0.f, 0.f, 0.f, 0.f);
#pragma unroll
            for (int k = 0; k < RCHUNKS; k++) {
                const float4* src = (const float4*)g_S2
                                  + (size_t)(b * RCHUNKS + k) * (SLOTS * CC / 4) + i;
                s = f4add(s, __ldcg(src));
            }
            ((float4*)sS)[i] = s;
        }
        __syncthreads();

        const int oc  = tid & 63;
        const int sub = tid >> 6;
        const int j0  = sub * 576;

        float acc = 0.f;
#pragma unroll 8
        for (int j = 0; j < 576; j++)
            acc = fmaf(sS[j0 + j], conv_w[(size_t)(j0 + j) * COUT + oc], acc);

        __shared__ float part[4][COUT];
        part[sub][oc] = acc;
        __syncthreads();

        __shared__ float sp[COUT];
        __shared__ float slog[ROUTES];
        if (tid < COUT) {
            sp[tid] = (part[0][tid] + part[1][tid] + part[2][tid] + part[3][tid])
                      * (1.0f / 729.0f) + conv_b[tid];
        }
        __syncthreads();

        if (tid < ROUTES) {
            float l = fc_b[tid];
#pragma unroll
            for (int j = 0; j < COUT; j++)
                l = fmaf(sp[j], fc_w[j * ROUTES + tid], l);
            slog[tid] = l;
            out_logits[b * ROUTES + tid] = l;
        }
        __syncthreads();

        if (tid == 0) {
            float best = slog[0];
            int br = 0;
#pragma unroll
            for (int r = 1; r < ROUTES; r++)
                if (slog[r] > best) { best = slog[r]; br = r; }  // first-max == argmax
            g_route[b] = br;
            __threadfence();                       // release
            g_ready[b] = 1;
        }
    }

    // ================= PHASE 3: gather own-batch tile slice ==================
    __shared__ int s_route;
    if (tid == 0) {
        while (g_ready[b] == 0) { __nanosleep(64); }
        __threadfence();                           // acquire
        s_route = g_route[b];
    }
    __syncthreads();
    const int r = s_route;

    const int t0 = (GTILES * chunk) / RCHUNKS;         // static slice: 3-4 tiles
    const int t1 = (GTILES * (chunk + 1)) / RCHUNKS;

    for (int t = t0; t < t1; t++) {
        const size_t base_pix = (size_t)b * (HH * WW) + (size_t)t * 64;
        const float4* src = (const float4*)in + base_pix * (CC / 4) + r * (RW / 4);
        float4* dst = (float4*)out_x + base_pix * (RW / 4);
#pragma unroll
        for (int k = 0; k < 4; k++) {
            const int item = tid + k * 256;        // 0..1023 = 64 px x 16 float4
            const int p = item >> 4;
            const int j = item & 15;
            dst[item] = src[(size_t)p * (CC / 4) + j];
        }
    }
    __syncthreads();

    // last gatherer of batch resets flags for the next graph replay
    if (tid == 0) {
        int old = atomicAdd(&g_gcnt[b], 1);
        if (old == RCHUNKS - 1) {
            g_gcnt[b] = 0;
            g_ready[b] = 0;
        }
    }
}

// ---------------------------------------------------------------------------
extern "C" void kernel_launch(void* const* d_in, const int* in_sizes, int n_in,
                              void* d_out, int out_size) {
    const float* in     = (const float*)d_in[0];
    const float* conv_w = (const float*)d_in[1];
    const float* conv_b = (const float*)d_in[2];
    const float* fc_w   = (const float*)d_in[3];
    const float* fc_b   = (const float*)d_in[4];

    float* out        = (float*)d_out;
    float* out_logits = out + (size_t)BB * HH * WW * RW;  // x first, then logits

    routing_fused_kernel<<<BB * RCHUNKS, 256>>>(in, conv_w, conv_b, fc_w, fc_b,
                                                out_logits, out);
}

// round 11
// speedup vs baseline: 1.9487x; 1.9487x over previous
#include <cuda_runtime.h>

#define BB 64
#define HH 56
#define WW 56
#define CC 256
#define COUT 64
#define ROUTES 4
#define RW (CC / ROUTES)          // 64 channels per route
#define RCHUNKS 14                // 4 rows per chunk
#define SLOTS 9                   // 3x3 (dh,dw) classes
#define NQ (SLOTS * CC / 4)       // 576 float4 quads per batch image sum

// per-(batch,chunk) partial patch sums: [BB][RCHUNKS][SLOTS][CC] floats (~8 MB)
__device__ float g_S2[BB * RCHUNKS * SLOTS * CC];
// composed routing weights: W2[i][r] = (conv_w @ fc_w)[i][r] / 729   (2304 x 4)
__device__ float g_W2[SLOTS * CC * ROUTES];
__device__ float g_C[ROUTES];     // c[r] = conv_b @ fc_w + fc_b
__device__ int   g_route[BB];

__device__ __forceinline__ float4 f4add(float4 a, float4 b) {
    return make_float4(a.x + b.x, a.y + b.y, a.z + b.z, a.w + b.w);
}
__device__ __forceinline__ float4 f4sub(float4 a, float4 b) {
    return make_float4(a.x - b.x, a.y - b.y, a.z - b.z, a.w - b.w);
}
__device__ __forceinline__ float4 f4fma(float s, float4 w, float4 acc) {
    return make_float4(fmaf(s, w.x, acc.x), fmaf(s, w.y, acc.y),
                       fmaf(s, w.z, acc.z), fmaf(s, w.w, acc.w));
}

// ---------------------------------------------------------------------------
// K1: streaming patch-sum reduction (grid y < 14) + piggybacked W2 composition
// (grid y == 14, 64 cheap blocks that overlap the stream).
// Patch block = (batch, 4-row chunk), 256 threads = 64 channel-quads x 4 rows.
// Per row: even/odd running float4 sums + edge captures -> 3 dw-class sums;
// reducer (rt==0) applies h-parity/boundary logic, stores 9 slots to scratch.
// ---------------------------------------------------------------------------
__global__ __launch_bounds__(256) void patch_w2_kernel(const float* __restrict__ in,
                                                       const float* __restrict__ conv_w,
                                                       const float* __restrict__ conv_b,
                                                       const float* __restrict__ fc_w,
                                                       const float* __restrict__ fc_b) {
    const int b     = blockIdx.x;
    const int chunk = blockIdx.y;          // 0..14
    const int tid   = threadIdx.x;

    if (chunk == RCHUNKS) {
        // ---- W2 strip: rows [b*36, (b+1)*36), 4 routes each -----------------
        if (tid < 144) {
            const int i = b * 36 + (tid >> 2);
            const int r = tid & 3;
            float s = 0.f;
#pragma unroll 16
            for (int o = 0; o < COUT; o++)
                s = fmaf(conv_w[(size_t)i * COUT + o], fc_w[o * ROUTES + r], s);
            g_W2[i * ROUTES + r] = s * (1.0f / 729.0f);
        } else if (b == 0 && tid >= 160 && tid < 160 + ROUTES) {
            const int r = tid - 160;
            float s = fc_b[r];
            for (int o = 0; o < COUT; o++)
                s = fmaf(conv_b[o], fc_w[o * ROUTES + r], s);
            g_C[r] = s;
        }
        return;
    }

    const int q  = tid & 63;               // channel quad 0..63
    const int rt = tid >> 6;               // row-thread 0..3
    const int h  = chunk * 4 + rt;

    const float4* row = (const float4*)in
                      + ((size_t)(b * HH + h) * WW) * (CC / 4) + q;

    float4 e = make_float4(0.f, 0.f, 0.f, 0.f);
    float4 o = make_float4(0.f, 0.f, 0.f, 0.f);
    float4 v0, v54, v55;
#pragma unroll
    for (int w = 0; w < WW; w += 2) {
        float4 a  = row[(size_t)w * (CC / 4)];
        float4 bb = row[(size_t)(w + 1) * (CC / 4)];
        if (w == 0)  { v0 = a; }
        if (w == 54) { v54 = a; v55 = bb; }
        e = f4add(e, a);
        o = f4add(o, bb);
    }

    __shared__ float4 sacc[4][3][64];
    sacc[rt][0][q] = f4sub(e, v54);  // W0: even w in [0,52]
    sacc[rt][1][q] = f4sub(o, v55);  // W1: odd  w in [1,53]
    sacc[rt][2][q] = f4sub(e, v0);   // W2: even w in [2,54]
    __syncthreads();

    if (rt == 0) {
        float4 outv[SLOTS];
#pragma unroll
        for (int s = 0; s < SLOTS; s++) outv[s] = make_float4(0.f, 0.f, 0.f, 0.f);

#pragma unroll
        for (int r = 0; r < 4; r++) {
            const int hh = chunk * 4 + r;
            const float4 W0 = sacc[r][0][q];
            const float4 W1 = sacc[r][1][q];
            const float4 W2 = sacc[r][2][q];
            if ((hh & 1) == 0) {
                if (hh <= 52) { outv[0] = f4add(outv[0], W0); outv[1] = f4add(outv[1], W1); outv[2] = f4add(outv[2], W2); }
                if (hh >= 2)  { outv[6] = f4add(outv[6], W0); outv[7] = f4add(outv[7], W1); outv[8] = f4add(outv[8], W2); }
            } else {
                if (hh <= 53) { outv[3] = f4add(outv[3], W0); outv[4] = f4add(outv[4], W1); outv[5] = f4add(outv[5], W2); }
            }
        }

        float4* dst = (float4*)g_S2 + ((size_t)(b * RCHUNKS + chunk) * SLOTS) * (CC / 4) + q;
#pragma unroll
        for (int s = 0; s < SLOTS; s++)
            dst[(size_t)s * (CC / 4)] = outv[s];
    }
}

// ---------------------------------------------------------------------------
// K2: per-batch logits + route via composed W2 (no pooled GEMM, no long
// chains). One block per batch, 256 threads. Each thread strip-mines the 576
// i-quads: sum 14 L2-hot chunk partials, fused float4-dot against W2 rows.
// Warp-shuffle + smem reduction -> logits(4) + argmax -> route.
// ---------------------------------------------------------------------------
__global__ __launch_bounds__(256) void logits_route_kernel(float* __restrict__ out_logits) {
    const int b   = blockIdx.x;
    const int tid = threadIdx.x;

    float4 acc = make_float4(0.f, 0.f, 0.f, 0.f);

    for (int q4 = tid; q4 < NQ; q4 += 256) {
        float4 s = make_float4(0.f, 0.f, 0.f, 0.f);
#pragma unroll
        for (int k = 0; k < RCHUNKS; k++) {
            const float4* src = (const float4*)g_S2
                              + (size_t)(b * RCHUNKS + k) * NQ + q4;
            s = f4add(s, __ldcg(src));
        }
        const float4* w2 = (const float4*)g_W2 + q4 * 4;  // rows i=4q4..4q4+3
        acc = f4fma(s.x, w2[0], acc);
        acc = f4fma(s.y, w2[1], acc);
        acc = f4fma(s.z, w2[2], acc);
        acc = f4fma(s.w, w2[3], acc);
    }

    // warp reduction
#pragma unroll
    for (int off = 16; off > 0; off >>= 1) {
        acc.x += __shfl_xor_sync(0xFFFFFFFFu, acc.x, off);
        acc.y += __shfl_xor_sync(0xFFFFFFFFu, acc.y, off);
        acc.z += __shfl_xor_sync(0xFFFFFFFFu, acc.z, off);
        acc.w += __shfl_xor_sync(0xFFFFFFFFu, acc.w, off);
    }

    __shared__ float4 wred[8];
    if ((tid & 31) == 0) wred[tid >> 5] = acc;
    __syncthreads();

    if (tid == 0) {
        float4 tot = wred[0];
#pragma unroll
        for (int wg = 1; wg < 8; wg++) tot = f4add(tot, wred[wg]);

        float l[ROUTES];
        l[0] = tot.x + g_C[0];
        l[1] = tot.y + g_C[1];
        l[2] = tot.z + g_C[2];
        l[3] = tot.w + g_C[3];

        float best = l[0];
        int br = 0;
#pragma unroll
        for (int r = 1; r < ROUTES; r++)
            if (l[r] > best) { best = l[r]; br = r; }   // first-max == argmax
        g_route[b] = br;

        out_logits[b * ROUTES + 0] = l[0];
        out_logits[b * ROUTES + 1] = l[1];
        out_logits[b * ROUTES + 2] = l[2];
        out_logits[b * ROUTES + 3] = l[3];
    }
}

// ---------------------------------------------------------------------------
// K3: routed channel-group gather (measured-best config, at its traffic floor).
// Block = (batch, 64-pixel tile), 4 independent float4 copies per thread.
// ---------------------------------------------------------------------------
__global__ __launch_bounds__(256) void gather_kernel(const float4* __restrict__ in4,
                                                     float4* __restrict__ out4) {
    const int b = blockIdx.x;
    const int r = g_route[b];
    const size_t base_pix = (size_t)b * (HH * WW) + (size_t)blockIdx.y * 64;
    const float4* src = in4 + base_pix * (CC / 4) + r * (RW / 4);
    float4* dst = out4 + base_pix * (RW / 4);

    const int t = threadIdx.x;
#pragma unroll
    for (int k = 0; k < 4; k++) {
        const int item = t + k * 256;      // 0..1023 = 64 pixels x 16 float4
        const int p = item >> 4;
        const int j = item & 15;
        dst[item] = src[(size_t)p * (CC / 4) + j];
    }
}

// ---------------------------------------------------------------------------
extern "C" void kernel_launch(void* const* d_in, const int* in_sizes, int n_in,
                              void* d_out, int out_size) {
    const float* in     = (const float*)d_in[0];
    const float* conv_w = (const float*)d_in[1];
    const float* conv_b = (const float*)d_in[2];
    const float* fc_w   = (const float*)d_in[3];
    const float* fc_b   = (const float*)d_in[4];

    float* out        = (float*)d_out;
    float* out_logits = out + (size_t)BB * HH * WW * RW;  // x first, then logits

    patch_w2_kernel<<<dim3(BB, RCHUNKS + 1), 256>>>(in, conv_w, conv_b, fc_w, fc_b);
    logits_route_kernel<<<BB, 256>>>(out_logits);
    gather_kernel<<<dim3(BB, HH * WW / 64), 256>>>((const float4*)in, (float4*)out);
}